// round 15
// baseline (speedup 1.0000x reference)
#include <cuda_runtime.h>
#include <cuda_bf16.h>
#include <math.h>
#include <stdint.h>

#define Bsz 2
#define Tsz 1024
#define Dsz 1024
#define Hn  16
#define HDim 64
#define En  8
#define FFn 4096
#define Ntok (Bsz*Tsz)
#define NROWS (Ntok*2)
#define EPSf 1e-5f
#define WELEM (En*Dsz*FFn)

__device__ __align__(1024) float g_xn  [Ntok*Dsz];
__device__ __align__(1024) float g_x1  [Ntok*Dsz];
__device__ __align__(1024) float g_y   [(size_t)NROWS*Dsz];
__device__ __align__(1024) __nv_bfloat16 g_xnb  [Ntok*Dsz];
__device__ __align__(1024) __nv_bfloat16 g_qkvb [Ntok*3*Dsz];
__device__ __align__(1024) __nv_bfloat16 g_attnb[Ntok*Dsz];
__device__ __align__(1024) __nv_bfloat16 g_xgb[(size_t)NROWS*Dsz];
__device__ __align__(1024) __nv_bfloat16 g_hb [(size_t)NROWS*FFn];
__device__ __align__(1024) __nv_bfloat16 g_w1b[(size_t)WELEM];
__device__ __align__(1024) __nv_bfloat16 g_w2b[(size_t)WELEM];
__device__ __align__(1024) __nv_bfloat16 g_wpb[(size_t)WELEM];
__device__ __align__(1024) __nv_bfloat16 g_wqb[Dsz*3*Dsz];
__device__ __align__(1024) __nv_bfloat16 g_wob[Dsz*Dsz];
__device__ int   g_counts[En];
__device__ int   g_offsets[En];
__device__ int   g_cursor[En];
__device__ int   g_rowmap[NROWS];
__device__ int2  g_eidx [Ntok];
__device__ float2 g_gates[Ntok];

// ============ PTX helpers ============
__device__ __forceinline__ uint32_t s2u(const void* p) {
    uint32_t a;
    asm("{ .reg .u64 t; cvta.to.shared.u64 t, %1; cvt.u32.u64 %0, t; }" : "=r"(a) : "l"(p));
    return a;
}
#define CPA16(dst,src) asm volatile("cp.async.cg.shared.global [%0], [%1], 16;" :: "r"((uint32_t)(dst)), "l"(src) : "memory")
#define CPA_COMMIT()   asm volatile("cp.async.commit_group;" ::: "memory")
#define CPA_WAIT3()    asm volatile("cp.async.wait_group 3;" ::: "memory")
#define CPA_WAIT2()    asm volatile("cp.async.wait_group 2;" ::: "memory")
#define CPA_WAIT1()    asm volatile("cp.async.wait_group 1;" ::: "memory")
#define CPA_WAIT0()    asm volatile("cp.async.wait_group 0;" ::: "memory")

__device__ __forceinline__ void mma_bf16(float* c, const uint32_t* a, uint32_t b0, uint32_t b1)
{
    asm volatile("mma.sync.aligned.m16n8k16.row.col.f32.bf16.bf16.f32 "
        "{%0,%1,%2,%3}, {%4,%5,%6,%7}, {%8,%9}, {%0,%1,%2,%3};"
        : "+f"(c[0]), "+f"(c[1]), "+f"(c[2]), "+f"(c[3])
        : "r"(a[0]), "r"(a[1]), "r"(a[2]), "r"(a[3]), "r"(b0), "r"(b1));
}

#define LDM_X4(r, addr) \
    asm volatile("ldmatrix.sync.aligned.m8n8.x4.shared.b16 {%0,%1,%2,%3}, [%4];" \
        : "=r"((r)[0]), "=r"((r)[1]), "=r"((r)[2]), "=r"((r)[3]) : "r"(addr))
#define LDM_X4T(r, addr) \
    asm volatile("ldmatrix.sync.aligned.m8n8.x4.trans.shared.b16 {%0,%1,%2,%3}, [%4];" \
        : "=r"((r)[0]), "=r"((r)[1]), "=r"((r)[2]), "=r"((r)[3]) : "r"(addr))

// ============ bf16 tile geometry ============
#define SA 40
#define SB 136
#define A_BYTES (128*SA*2)
#define B_BYTES (32*SB*2)
#define UPSTG (A_BYTES + 2*B_BYTES)
#define DNSTG (A_BYTES + B_BYTES)
#define SMEM_UPB (4*UPSTG)
#define SMEM_DNB (4*DNSTG)

// ============ dense bf16 GEMM. MODE 1: fp32 out + resid; MODE 2: bf16 out ============
template<int MODE>
__global__ void __launch_bounds__(256) tc_gemm_bf16(const __nv_bfloat16* __restrict__ A,
                                                    const __nv_bfloat16* __restrict__ B,
                                                    const float* __restrict__ bias,
                                                    const float* __restrict__ resid,
                                                    void* __restrict__ Cout,
                                                    int Nt, int K)
{
    int row0 = blockIdx.y * 128, col0 = blockIdx.x * 128;
    extern __shared__ char smemc[];
    uint32_t smem_u = s2u(smemc);
    int tid = threadIdx.x, lane = tid & 31, wid = tid >> 5;
    int warp_m = wid >> 2, warp_n = wid & 3;
    int lr = lane >> 2, lc = lane & 3;

    float c[4][4][4];
    #pragma unroll
    for (int i = 0; i < 4; i++)
        #pragma unroll
        for (int j = 0; j < 4; j++)
            #pragma unroll
            for (int q = 0; q < 4; q++) c[i][j][q] = 0.f;

    auto load_block = [&](int kb, int s) {
        uint32_t aS = smem_u + s * DNSTG;
        uint32_t bS = aS + A_BYTES;
        #pragma unroll
        for (int i = 0; i < 2; i++) {
            int cc = i * 256 + tid;
            int r = cc >> 2, c8 = cc & 3;
            CPA16(aS + (r * SA + c8 * 8) * 2, A + (size_t)(row0 + r) * K + kb * 32 + c8 * 8);
        }
        #pragma unroll
        for (int i = 0; i < 2; i++) {
            int cc = i * 256 + tid;
            int kr = cc >> 4, n8 = cc & 15;
            CPA16(bS + (kr * SB + n8 * 8) * 2, B + (size_t)(kb * 32 + kr) * Nt + col0 + n8 * 8);
        }
        CPA_COMMIT();
    };

    int NK = K >> 5;
    load_block(0, 0); load_block(1, 1); load_block(2, 2); load_block(3, 3);

    for (int ks = 0; ks < NK; ks++) {
        int s = ks & 3;
        int allow = NK - 1 - ks; if (allow > 3) allow = 3;
        if (allow == 3) CPA_WAIT3(); else if (allow == 2) CPA_WAIT2();
        else if (allow == 1) CPA_WAIT1(); else CPA_WAIT0();
        __syncthreads();
        uint32_t aS = smem_u + s * DNSTG;
        uint32_t bS = aS + A_BYTES;
        #pragma unroll
        for (int k16 = 0; k16 < 2; k16++) {
            uint32_t af[4][4], bf[2][4];
            #pragma unroll
            for (int mt = 0; mt < 4; mt++) {
                uint32_t addr = aS + ((warp_m * 64 + mt * 16 + (lane & 15)) * SA
                                      + k16 * 16 + (lane >> 4) * 8) * 2;
                LDM_X4(af[mt], addr);
            }
            #pragma unroll
            for (int nh = 0; nh < 2; nh++) {
                uint32_t boff = ((k16 * 16 + (lane & 15)) * SB
                                 + warp_n * 32 + nh * 16 + (lane >> 4) * 8) * 2;
                LDM_X4T(bf[nh], bS + boff);
            }
            #pragma unroll
            for (int mt = 0; mt < 4; mt++)
                #pragma unroll
                for (int nt = 0; nt < 4; nt++) {
                    int nh = nt >> 1, p = (nt & 1) * 2;
                    mma_bf16(c[mt][nt], af[mt], bf[nh][p], bf[nh][p + 1]);
                }
        }
        __syncthreads();
        if (ks + 4 < NK) load_block(ks + 4, s);
    }

    #pragma unroll
    for (int mt = 0; mt < 4; mt++) {
        #pragma unroll
        for (int half = 0; half < 2; half++) {
            int orow = row0 + warp_m * 64 + mt * 16 + lr + half * 8;
            #pragma unroll
            for (int nt = 0; nt < 4; nt++) {
                int coll = warp_n * 32 + nt * 8 + lc * 2;
                float v0 = c[mt][nt][half*2]   + bias[col0 + coll];
                float v1 = c[mt][nt][half*2+1] + bias[col0 + coll + 1];
                if (MODE == 1) {
                    const float* Rrow = resid + (size_t)orow * Nt + col0;
                    float2 rv = *(const float2*)(Rrow + coll);
                    v0 += rv.x; v1 += rv.y;
                    *(float2*)((float*)Cout + (size_t)orow * Nt + col0 + coll) = make_float2(v0, v1);
                } else {
                    *(__nv_bfloat162*)((__nv_bfloat16*)Cout + (size_t)orow * Nt + col0 + coll)
                        = __floats2bfloat162_rn(v0, v1);
                }
            }
        }
    }
}

// ============ MoE up (R13 dual-accumulator; grid: x=row-block, y=col-block) ============
__global__ void __launch_bounds__(256) moe_up_bf16(const float* __restrict__ b1,
                                                   const float* __restrict__ b2)
{
    int e = blockIdx.z;
    int cnt = g_counts[e];
    int row0 = blockIdx.x * 128, col0 = blockIdx.y * 128;
    if (row0 >= cnt) return;
    int rowbase = g_offsets[e] + row0;
    b1 += (size_t)e * FFn; b2 += (size_t)e * FFn;
    const __nv_bfloat16* W1 = g_w1b + (size_t)e * Dsz * FFn;
    const __nv_bfloat16* W2 = g_w2b + (size_t)e * Dsz * FFn;

    extern __shared__ char smemc[];
    uint32_t smem_u = s2u(smemc);
    int tid = threadIdx.x, lane = tid & 31, wid = tid >> 5;
    int warp_m = wid >> 2, warp_n = wid & 3;
    int lr = lane >> 2, lc = lane & 3;

    float c1[4][4][4], c2[4][4][4];
    #pragma unroll
    for (int i = 0; i < 4; i++)
        #pragma unroll
        for (int j = 0; j < 4; j++)
            #pragma unroll
            for (int q = 0; q < 4; q++) { c1[i][j][q] = 0.f; c2[i][j][q] = 0.f; }

    auto load_block = [&](int kb, int s) {
        uint32_t aS = smem_u + s * UPSTG;
        uint32_t b1S = aS + A_BYTES, b2S = b1S + B_BYTES;
        #pragma unroll
        for (int i = 0; i < 2; i++) {
            int c = i * 256 + tid;
            int r = c >> 2, c8 = c & 3;
            int gr = rowbase + r; if (gr > NROWS - 1) gr = NROWS - 1;
            CPA16(aS + (r * SA + c8 * 8) * 2, g_xgb + (size_t)gr * Dsz + kb * 32 + c8 * 8);
        }
        #pragma unroll
        for (int i = 0; i < 2; i++) {
            int c = i * 256 + tid;
            int kr = c >> 4, n8 = c & 15;
            size_t off = (size_t)(kb * 32 + kr) * FFn + col0 + n8 * 8;
            CPA16(b1S + (kr * SB + n8 * 8) * 2, W1 + off);
            CPA16(b2S + (kr * SB + n8 * 8) * 2, W2 + off);
        }
        CPA_COMMIT();
    };

    const int NK = Dsz >> 5;
    load_block(0, 0); load_block(1, 1); load_block(2, 2); load_block(3, 3);

    for (int ks = 0; ks < NK; ks++) {
        int s = ks & 3;
        int allow = NK - 1 - ks; if (allow > 3) allow = 3;
        if (allow == 3) CPA_WAIT3(); else if (allow == 2) CPA_WAIT2();
        else if (allow == 1) CPA_WAIT1(); else CPA_WAIT0();
        __syncthreads();
        uint32_t aS = smem_u + s * UPSTG;
        uint32_t b1S = aS + A_BYTES, b2S = b1S + B_BYTES;
        #pragma unroll
        for (int k16 = 0; k16 < 2; k16++) {
            uint32_t af[4][4], bfA[2][4], bfB[2][4];
            #pragma unroll
            for (int mt = 0; mt < 4; mt++) {
                uint32_t addr = aS + ((warp_m * 64 + mt * 16 + (lane & 15)) * SA
                                      + k16 * 16 + (lane >> 4) * 8) * 2;
                LDM_X4(af[mt], addr);
            }
            #pragma unroll
            for (int nh = 0; nh < 2; nh++) {
                uint32_t boff = ((k16 * 16 + (lane & 15)) * SB
                                 + warp_n * 32 + nh * 16 + (lane >> 4) * 8) * 2;
                LDM_X4T(bfA[nh], b1S + boff);
                LDM_X4T(bfB[nh], b2S + boff);
            }
            #pragma unroll
            for (int mt = 0; mt < 4; mt++)
                #pragma unroll
                for (int nt = 0; nt < 4; nt++) {
                    int nh = nt >> 1, p = (nt & 1) * 2;
                    mma_bf16(c1[mt][nt], af[mt], bfA[nh][p], bfA[nh][p + 1]);
                    mma_bf16(c2[mt][nt], af[mt], bfB[nh][p], bfB[nh][p + 1]);
                }
        }
        __syncthreads();
        if (ks + 4 < NK) load_block(ks + 4, s);
    }

    #pragma unroll
    for (int mt = 0; mt < 4; mt++) {
        #pragma unroll
        for (int half = 0; half < 2; half++) {
            int lrow = warp_m * 64 + mt * 16 + lr + half * 8;
            if ((row0 + lrow) >= cnt) continue;
            __nv_bfloat16* Hrow = g_hb + (size_t)(rowbase + lrow) * FFn + col0;
            #pragma unroll
            for (int nt = 0; nt < 4; nt++) {
                int coll = warp_n * 32 + nt * 8 + lc * 2;
                float u0 = c1[mt][nt][half*2]   + b1[col0 + coll];
                float u1 = c1[mt][nt][half*2+1] + b1[col0 + coll + 1];
                float v0 = c2[mt][nt][half*2]   + b2[col0 + coll];
                float v1 = c2[mt][nt][half*2+1] + b2[col0 + coll + 1];
                float h0 = u0 / (1.f + __expf(-u0)) * v0;
                float h1 = u1 / (1.f + __expf(-u1)) * v1;
                *(__nv_bfloat162*)(Hrow + coll) = __floats2bfloat162_rn(h0, h1);
            }
        }
    }
}

// ============ MoE down (grid: x=row-block, y=col-block) ============
__global__ void __launch_bounds__(256) moe_down_bf16(const float* __restrict__ bp)
{
    int e = blockIdx.z;
    int cnt = g_counts[e];
    int row0 = blockIdx.x * 128, col0 = blockIdx.y * 128;
    if (row0 >= cnt) return;
    int rowbase = g_offsets[e] + row0;
    bp += (size_t)e * Dsz;
    const __nv_bfloat16* Wp = g_wpb + (size_t)e * FFn * Dsz;

    extern __shared__ char smemc[];
    uint32_t smem_u = s2u(smemc);
    int tid = threadIdx.x, lane = tid & 31, wid = tid >> 5;
    int warp_m = wid >> 2, warp_n = wid & 3;
    int lr = lane >> 2, lc = lane & 3;

    float c[4][4][4];
    #pragma unroll
    for (int i = 0; i < 4; i++)
        #pragma unroll
        for (int j = 0; j < 4; j++)
            #pragma unroll
            for (int q = 0; q < 4; q++) c[i][j][q] = 0.f;

    auto load_block = [&](int kb, int s) {
        uint32_t aS = smem_u + s * DNSTG;
        uint32_t bS = aS + A_BYTES;
        #pragma unroll
        for (int i = 0; i < 2; i++) {
            int cc = i * 256 + tid;
            int r = cc >> 2, c8 = cc & 3;
            int gr = rowbase + r; if (gr > NROWS - 1) gr = NROWS - 1;
            CPA16(aS + (r * SA + c8 * 8) * 2, g_hb + (size_t)gr * FFn + kb * 32 + c8 * 8);
        }
        #pragma unroll
        for (int i = 0; i < 2; i++) {
            int cc = i * 256 + tid;
            int kr = cc >> 4, n8 = cc & 15;
            CPA16(bS + (kr * SB + n8 * 8) * 2, Wp + (size_t)(kb * 32 + kr) * Dsz + col0 + n8 * 8);
        }
        CPA_COMMIT();
    };

    const int NK = FFn >> 5;
    load_block(0, 0); load_block(1, 1); load_block(2, 2); load_block(3, 3);

    for (int ks = 0; ks < NK; ks++) {
        int s = ks & 3;
        int allow = NK - 1 - ks; if (allow > 3) allow = 3;
        if (allow == 3) CPA_WAIT3(); else if (allow == 2) CPA_WAIT2();
        else if (allow == 1) CPA_WAIT1(); else CPA_WAIT0();
        __syncthreads();
        uint32_t aS = smem_u + s * DNSTG;
        uint32_t bS = aS + A_BYTES;
        #pragma unroll
        for (int k16 = 0; k16 < 2; k16++) {
            uint32_t af[4][4], bf[2][4];
            #pragma unroll
            for (int mt = 0; mt < 4; mt++) {
                uint32_t addr = aS + ((warp_m * 64 + mt * 16 + (lane & 15)) * SA
                                      + k16 * 16 + (lane >> 4) * 8) * 2;
                LDM_X4(af[mt], addr);
            }
            #pragma unroll
            for (int nh = 0; nh < 2; nh++) {
                uint32_t boff = ((k16 * 16 + (lane & 15)) * SB
                                 + warp_n * 32 + nh * 16 + (lane >> 4) * 8) * 2;
                LDM_X4T(bf[nh], bS + boff);
            }
            #pragma unroll
            for (int mt = 0; mt < 4; mt++)
                #pragma unroll
                for (int nt = 0; nt < 4; nt++) {
                    int nh = nt >> 1, p = (nt & 1) * 2;
                    mma_bf16(c[mt][nt], af[mt], bf[nh][p], bf[nh][p + 1]);
                }
        }
        __syncthreads();
        if (ks + 4 < NK) load_block(ks + 4, s);
    }

    #pragma unroll
    for (int mt = 0; mt < 4; mt++) {
        #pragma unroll
        for (int half = 0; half < 2; half++) {
            int lrow = warp_m * 64 + mt * 16 + lr + half * 8;
            if ((row0 + lrow) >= cnt) continue;
            int packed = g_rowmap[rowbase + lrow];
            float* Yrow = g_y + (size_t)packed * Dsz + col0;
            #pragma unroll
            for (int nt = 0; nt < 4; nt++) {
                int coll = warp_n * 32 + nt * 8 + lc * 2;
                float v0 = c[mt][nt][half*2]   + bp[col0 + coll];
                float v1 = c[mt][nt][half*2+1] + bp[col0 + coll + 1];
                *(float2*)(Yrow + coll) = make_float2(v0, v1);
            }
        }
    }
}

// ============ weight conversions ============
__global__ void __launch_bounds__(256) convert_weights(const float* __restrict__ w1,
                                                       const float* __restrict__ w2,
                                                       const float* __restrict__ wp)
{
    size_t base = ((size_t)blockIdx.x * 256 + threadIdx.x) * 8;
    const float* src = (blockIdx.y == 0) ? w1 : (blockIdx.y == 1) ? w2 : wp;
    __nv_bfloat16* dst = (blockIdx.y == 0) ? g_w1b : (blockIdx.y == 1) ? g_w2b : g_wpb;
    float4 a = *(const float4*)(src + base);
    float4 b = *(const float4*)(src + base + 4);
    __nv_bfloat162 r[4];
    r[0] = __floats2bfloat162_rn(a.x, a.y);
    r[1] = __floats2bfloat162_rn(a.z, a.w);
    r[2] = __floats2bfloat162_rn(b.x, b.y);
    r[3] = __floats2bfloat162_rn(b.z, b.w);
    *(uint4*)(dst + base) = *(uint4*)r;
}

__global__ void __launch_bounds__(256) convert_attn_weights(const float* __restrict__ wq,
                                                            const float* __restrict__ wo)
{
    size_t base = ((size_t)blockIdx.x * 256 + threadIdx.x) * 8;
    const float* src; __nv_bfloat16* dst;
    if (blockIdx.y == 0) { src = wq; dst = g_wqb; }
    else { if (base >= (size_t)Dsz * Dsz) return; src = wo; dst = g_wob; }
    float4 a = *(const float4*)(src + base);
    float4 b = *(const float4*)(src + base + 4);
    __nv_bfloat162 r[4];
    r[0] = __floats2bfloat162_rn(a.x, a.y);
    r[1] = __floats2bfloat162_rn(a.z, a.w);
    r[2] = __floats2bfloat162_rn(b.x, b.y);
    r[3] = __floats2bfloat162_rn(b.z, b.w);
    *(uint4*)(dst + base) = *(uint4*)r;
}

// ============ bf16 tensor-core flash attention (validated R13) ============
#define SK 72
#define ATT_SMEM ((128*SK + 4*64*SK + 128*SK)*2)

__global__ void __launch_bounds__(256) attn_mma_bf16(const __nv_bfloat16* __restrict__ qkv,
                                                     __nv_bfloat16* __restrict__ O)
{
    extern __shared__ __nv_bfloat16 smh[];
    __nv_bfloat16* Qs = smh;
    __nv_bfloat16* Kb = Qs + 128 * SK;
    __nv_bfloat16* Vb = Kb + 2 * 64 * SK;
    __nv_bfloat16* Ps = Vb + 2 * 64 * SK;
    const int qt = gridDim.x - 1 - blockIdx.x;
    const int h = blockIdx.y, b = blockIdx.z;
    const int q0 = qt * 128;
    int tid = threadIdx.x, lane = tid & 31, wid = tid >> 5;
    int lr = lane >> 2, lc = lane & 3;
    int wm = wid * 16;

    uint32_t qsU = s2u(Qs), kbU = s2u(Kb), vbU = s2u(Vb), psU = s2u(Ps);

    #pragma unroll
    for (int i = 0; i < 4; i++) {
        int idx = i * 256 + tid;
        int r = idx >> 3, c8 = idx & 7;
        CPA16(qsU + (r * SK + c8 * 8) * 2,
              qkv + (size_t)(b * Tsz + q0 + r) * (3 * Dsz) + h * HDim + c8 * 8);
    }
    CPA_COMMIT();

    auto loadKV = [&](int kt) {
        int s = kt & 1;
        uint32_t kU = kbU + s * 64 * SK * 2;
        uint32_t vU = vbU + s * 64 * SK * 2;
        int k0g = kt * 64;
        #pragma unroll
        for (int i = 0; i < 2; i++) {
            int idx = i * 256 + tid;
            int r = idx >> 3, c8 = idx & 7;
            const __nv_bfloat16* src = qkv + (size_t)(b * Tsz + k0g + r) * (3 * Dsz)
                                       + Dsz + h * HDim + c8 * 8;
            CPA16(kU + (r * SK + c8 * 8) * 2, src);
            CPA16(vU + (r * SK + c8 * 8) * 2, src + Dsz);
        }
        CPA_COMMIT();
    };

    float accO[8][4];
    #pragma unroll
    for (int nt = 0; nt < 8; nt++)
        #pragma unroll
        for (int q = 0; q < 4; q++) accO[nt][q] = 0.f;
    float m0 = -1e30f, m1 = -1e30f, l0 = 0.f, l1 = 0.f;

    int row0g = q0 + wm + lr, row1g = row0g + 8;
    int ktmax = qt * 2 + 2;

    int kn_row = (lane & 7) + ((lane >> 4) << 3);
    int kn_koff = ((lane >> 3) & 1) * 8;

    loadKV(0);
    for (int kt = 0; kt < ktmax; kt++) {
        int k0g = kt * 64;
        if (kt + 1 < ktmax) { loadKV(kt + 1); CPA_WAIT1(); }
        else CPA_WAIT0();
        __syncthreads();
        uint32_t ksU2 = kbU + (kt & 1) * 64 * SK * 2;
        uint32_t vsU2 = vbU + (kt & 1) * 64 * SK * 2;

        float cS[8][4];
        #pragma unroll
        for (int nt = 0; nt < 8; nt++)
            #pragma unroll
            for (int q = 0; q < 4; q++) cS[nt][q] = 0.f;
        #pragma unroll
        for (int k16 = 0; k16 < 4; k16++) {
            uint32_t aq[4];
            LDM_X4(aq, qsU + ((wm + (lane & 15)) * SK + k16 * 16 + (lane >> 4) * 8) * 2);
            #pragma unroll
            for (int nt2 = 0; nt2 < 4; nt2++) {
                uint32_t bk[4];
                LDM_X4(bk, ksU2 + ((nt2 * 16 + kn_row) * SK + k16 * 16 + kn_koff) * 2);
                mma_bf16(cS[nt2 * 2],     aq, bk[0], bk[1]);
                mma_bf16(cS[nt2 * 2 + 1], aq, bk[2], bk[3]);
            }
        }

        float mx0 = -1e30f, mx1 = -1e30f;
        #pragma unroll
        for (int nt = 0; nt < 8; nt++) {
            int colb = k0g + nt * 8 + 2 * lc;
            float s00 = cS[nt][0] * 0.125f; if (colb     > row0g) s00 = -1e30f;
            float s01 = cS[nt][1] * 0.125f; if (colb + 1 > row0g) s01 = -1e30f;
            float s10 = cS[nt][2] * 0.125f; if (colb     > row1g) s10 = -1e30f;
            float s11 = cS[nt][3] * 0.125f; if (colb + 1 > row1g) s11 = -1e30f;
            cS[nt][0] = s00; cS[nt][1] = s01; cS[nt][2] = s10; cS[nt][3] = s11;
            mx0 = fmaxf(mx0, fmaxf(s00, s01));
            mx1 = fmaxf(mx1, fmaxf(s10, s11));
        }
        mx0 = fmaxf(mx0, __shfl_xor_sync(0xffffffffu, mx0, 1));
        mx0 = fmaxf(mx0, __shfl_xor_sync(0xffffffffu, mx0, 2));
        mx1 = fmaxf(mx1, __shfl_xor_sync(0xffffffffu, mx1, 1));
        mx1 = fmaxf(mx1, __shfl_xor_sync(0xffffffffu, mx1, 2));
        float mn0 = fmaxf(m0, mx0), mn1 = fmaxf(m1, mx1);
        float ls0 = 0.f, ls1 = 0.f;
        __nv_bfloat16* pr0 = Ps + (wm + lr) * SK;
        __nv_bfloat16* pr1 = Ps + (wm + lr + 8) * SK;
        #pragma unroll
        for (int nt = 0; nt < 8; nt++) {
            float p00 = __expf(cS[nt][0] - mn0);
            float p01 = __expf(cS[nt][1] - mn0);
            float p10 = __expf(cS[nt][2] - mn1);
            float p11 = __expf(cS[nt][3] - mn1);
            ls0 += p00 + p01; ls1 += p10 + p11;
            int cb = nt * 8 + 2 * lc;
            *(__nv_bfloat162*)(pr0 + cb) = __floats2bfloat162_rn(p00, p01);
            *(__nv_bfloat162*)(pr1 + cb) = __floats2bfloat162_rn(p10, p11);
        }
        ls0 += __shfl_xor_sync(0xffffffffu, ls0, 1);
        ls0 += __shfl_xor_sync(0xffffffffu, ls0, 2);
        ls1 += __shfl_xor_sync(0xffffffffu, ls1, 1);
        ls1 += __shfl_xor_sync(0xffffffffu, ls1, 2);
        float alpha0 = __expf(m0 - mn0), alpha1 = __expf(m1 - mn1);
        m0 = mn0; m1 = mn1;
        l0 = l0 * alpha0 + ls0;
        l1 = l1 * alpha1 + ls1;
        #pragma unroll
        for (int nt = 0; nt < 8; nt++) {
            accO[nt][0] *= alpha0; accO[nt][1] *= alpha0;
            accO[nt][2] *= alpha1; accO[nt][3] *= alpha1;
        }
        __syncwarp();

        #pragma unroll
        for (int k16 = 0; k16 < 4; k16++) {
            uint32_t ap[4];
            LDM_X4(ap, psU + ((wm + (lane & 15)) * SK + k16 * 16 + (lane >> 4) * 8) * 2);
            #pragma unroll
            for (int nh = 0; nh < 4; nh++) {
                uint32_t bv[4];
                LDM_X4T(bv, vsU2 + ((k16 * 16 + (lane & 15)) * SK + nh * 16 + (lane >> 4) * 8) * 2);
                mma_bf16(accO[nh * 2],     ap, bv[0], bv[1]);
                mma_bf16(accO[nh * 2 + 1], ap, bv[2], bv[3]);
            }
        }
        __syncthreads();
    }

    float inv0 = 1.0f / l0, inv1 = 1.0f / l1;
    __nv_bfloat16* o0 = O + (size_t)(b * Tsz + row0g) * Dsz + h * HDim;
    __nv_bfloat16* o1 = O + (size_t)(b * Tsz + row1g) * Dsz + h * HDim;
    #pragma unroll
    for (int nt = 0; nt < 8; nt++) {
        int cb = nt * 8 + 2 * lc;
        *(__nv_bfloat162*)(o0 + cb) = __floats2bfloat162_rn(accO[nt][0] * inv0, accO[nt][1] * inv0);
        *(__nv_bfloat162*)(o1 + cb) = __floats2bfloat162_rn(accO[nt][2] * inv1, accO[nt][3] * inv1);
    }
}

// ============ elementwise / routing ============
template<bool WF32, bool WB16>
__global__ void __launch_bounds__(256) rmsnorm_kernel(const float* __restrict__ x,
                                                      const float* __restrict__ scale,
                                                      float* __restrict__ out,
                                                      __nv_bfloat16* __restrict__ outb)
{
    int n = blockIdx.x;
    const float* xr = x + (size_t)n * Dsz;
    float s = 0.f;
    for (int d = threadIdx.x; d < Dsz; d += 256) { float v = xr[d]; s += v * v; }
    __shared__ float red[8];
    for (int o = 16; o; o >>= 1) s += __shfl_xor_sync(0xffffffffu, s, o);
    if ((threadIdx.x & 31) == 0) red[threadIdx.x >> 5] = s;
    __syncthreads();
    if (threadIdx.x < 32) {
        float v = (threadIdx.x < 8) ? red[threadIdx.x] : 0.f;
        for (int o = 4; o; o >>= 1) v += __shfl_xor_sync(0xffffffffu, v, o);
        if (threadIdx.x == 0) red[0] = v;
    }
    __syncthreads();
    float inv = 1.0f / (sqrtf(red[0] / (float)Dsz) + EPSf);
    for (int d = threadIdx.x * 2; d < Dsz; d += 512) {
        float v0 = xr[d] * inv * scale[d];
        float v1 = xr[d + 1] * inv * scale[d + 1];
        if (WF32) *(float2*)(out + (size_t)n * Dsz + d) = make_float2(v0, v1);
        if (WB16) *(__nv_bfloat162*)(outb + (size_t)n * Dsz + d) = __floats2bfloat162_rn(v0, v1);
    }
}

__global__ void __launch_bounds__(256) rope_kernel(__nv_bfloat16* __restrict__ qkv)
{
    int i = blockIdx.x * 256 + threadIdx.x;
    int j = i & 31, h = (i >> 5) & 15, which = (i >> 9) & 1, n = i >> 10;
    int t = n & (Tsz - 1);
    float theta = powf(10000.0f, -(2.0f * (float)j) / (float)HDim);
    float s, c; sincosf((float)t * theta, &s, &c);
    __nv_bfloat16* base = qkv + (size_t)n * (3 * Dsz) + which * Dsz + h * HDim;
    float x1 = __bfloat162float(base[j]);
    float x2 = __bfloat162float(base[j + 32]);
    base[j]      = __float2bfloat16(x1 * c - x2 * s);
    base[j + 32] = __float2bfloat16(x1 * s + x2 * c);
}

__global__ void moe_init_kernel() {
    int i = threadIdx.x;
    if (i < En) { g_counts[i] = 0; g_cursor[i] = 0; }
}

__global__ void __launch_bounds__(256) gate_kernel(const float* __restrict__ xn,
                                                   const float* __restrict__ w_gate,
                                                   const float* __restrict__ b_gate)
{
    int n = blockIdx.x * 8 + (threadIdx.x >> 5);
    int lane = threadIdx.x & 31;
    float acc[En];
    #pragma unroll
    for (int e = 0; e < En; e++) acc[e] = 0.f;
    const float* xr = xn + (size_t)n * Dsz;
    for (int d = lane; d < Dsz; d += 32) {
        float xv = xr[d];
        const float* wr = w_gate + (size_t)d * En;
        #pragma unroll
        for (int e = 0; e < En; e++) acc[e] += xv * wr[e];
    }
    #pragma unroll
    for (int e = 0; e < En; e++)
        #pragma unroll
        for (int o = 16; o; o >>= 1) acc[e] += __shfl_xor_sync(0xffffffffu, acc[e], o);
    if (lane == 0) {
        #pragma unroll
        for (int e = 0; e < En; e++) acc[e] += b_gate[e];
        int e0 = 0; float v0 = acc[0];
        #pragma unroll
        for (int e = 1; e < En; e++) if (acc[e] > v0) { v0 = acc[e]; e0 = e; }
        int e1 = -1; float v1 = -1e30f;
        #pragma unroll
        for (int e = 0; e < En; e++) if (e != e0 && acc[e] > v1) { v1 = acc[e]; e1 = e; }
        float g0 = 1.0f / (1.0f + __expf(v1 - v0));
        atomicAdd(&g_counts[e0], 1);
        atomicAdd(&g_counts[e1], 1);
        g_eidx[n] = make_int2(e0, e1);
        g_gates[n] = make_float2(g0, 1.0f - g0);
    }
}

__global__ void moe_offsets_kernel(float* __restrict__ aux_out)
{
    if (threadIdx.x == 0) {
        int off = 0; float aux = 0.f;
        #pragma unroll
        for (int e = 0; e < En; e++) { g_offsets[e] = off; off += g_counts[e]; }
        #pragma unroll
        for (int e = 0; e < En; e++) {
            float f = (float)g_counts[e] / (float)NROWS - 1.0f / (float)En;
            aux += f * f;
        }
        *aux_out = aux;
    }
}

__global__ void __launch_bounds__(256) moe_scatter_kernel()
{
    int n = blockIdx.x * 256 + threadIdx.x;
    if (n >= Ntok) return;
    int2 e = g_eidx[n];
    int p0 = atomicAdd(&g_cursor[e.x], 1);
    g_rowmap[g_offsets[e.x] + p0] = n * 2;
    int p1 = atomicAdd(&g_cursor[e.y], 1);
    g_rowmap[g_offsets[e.y] + p1] = n * 2 + 1;
}

__global__ void __launch_bounds__(256) gather_kernel(const float* __restrict__ xn)
{
    int r = blockIdx.x;
    int tok = g_rowmap[r] >> 1;
    float4 v = *(const float4*)(xn + (size_t)tok * Dsz + threadIdx.x * 4);
    __nv_bfloat162 p0 = __floats2bfloat162_rn(v.x, v.y);
    __nv_bfloat162 p1 = __floats2bfloat162_rn(v.z, v.w);
    __nv_bfloat162 pr[2] = {p0, p1};
    *(uint2*)(g_xgb + (size_t)r * Dsz + threadIdx.x * 4) = *(uint2*)pr;
}

__global__ void __launch_bounds__(256) combine_kernel(const float* __restrict__ x1,
                                                      float* __restrict__ out)
{
    int i = blockIdx.x * 256 + threadIdx.x;
    int n = i >> 10, d = i & 1023;
    float2 g = g_gates[n];
    float y0 = g_y[(size_t)(n * 2) * Dsz + d];
    float y1 = g_y[(size_t)(n * 2 + 1) * Dsz + d];
    out[i] = x1[i] + g.x * y0 + g.y * y1;
}

// ============ launch ============
extern "C" void kernel_launch(void* const* d_in, const int* in_sizes, int n_in,
                              void* d_out, int out_size)
{
    const float* x      = (const float*)d_in[0];
    const float* w_qkv  = (const float*)d_in[1];
    const float* b_qkv  = (const float*)d_in[2];
    const float* w_out  = (const float*)d_in[3];
    const float* b_out  = (const float*)d_in[4];
    const float* scale1 = (const float*)d_in[5];
    const float* scale2 = (const float*)d_in[6];
    const float* w_gate = (const float*)d_in[7];
    const float* b_gate = (const float*)d_in[8];
    const float* w1     = (const float*)d_in[9];
    const float* b1     = (const float*)d_in[10];
    const float* w2     = (const float*)d_in[11];
    const float* b2     = (const float*)d_in[12];
    const float* wp     = (const float*)d_in[13];
    const float* bp     = (const float*)d_in[14];
    float* out = (float*)d_out;

    float* xn   = nullptr; cudaGetSymbolAddress((void**)&xn,   g_xn);
    float* x1   = nullptr; cudaGetSymbolAddress((void**)&x1,   g_x1);
    __nv_bfloat16* xnb   = nullptr; cudaGetSymbolAddress((void**)&xnb,   g_xnb);
    __nv_bfloat16* qkvb  = nullptr; cudaGetSymbolAddress((void**)&qkvb,  g_qkvb);
    __nv_bfloat16* attnb = nullptr; cudaGetSymbolAddress((void**)&attnb, g_attnb);
    __nv_bfloat16* wqb   = nullptr; cudaGetSymbolAddress((void**)&wqb,   g_wqb);
    __nv_bfloat16* wob   = nullptr; cudaGetSymbolAddress((void**)&wob,   g_wob);

    static cudaStream_t s2;
    static cudaEvent_t evA, evB;
    static bool init_done = false;
    if (!init_done) {
        cudaStreamCreateWithFlags(&s2, cudaStreamNonBlocking);
        cudaEventCreateWithFlags(&evA, cudaEventDisableTiming);
        cudaEventCreateWithFlags(&evB, cudaEventDisableTiming);
        cudaFuncSetAttribute(tc_gemm_bf16<1>, cudaFuncAttributeMaxDynamicSharedMemorySize, SMEM_DNB);
        cudaFuncSetAttribute(tc_gemm_bf16<2>, cudaFuncAttributeMaxDynamicSharedMemorySize, SMEM_DNB);
        cudaFuncSetAttribute(moe_up_bf16,     cudaFuncAttributeMaxDynamicSharedMemorySize, SMEM_UPB);
        cudaFuncSetAttribute(moe_down_bf16,   cudaFuncAttributeMaxDynamicSharedMemorySize, SMEM_DNB);
        cudaFuncSetAttribute(attn_mma_bf16,   cudaFuncAttributeMaxDynamicSharedMemorySize, ATT_SMEM);
        init_done = true;
    }

    cudaEventRecord(evA, 0);
    cudaStreamWaitEvent(s2, evA, 0);
    convert_weights<<<dim3(WELEM / 8 / 256, 3), 256, 0, s2>>>(w1, w2, wp);
    cudaEventRecord(evB, s2);

    convert_attn_weights<<<dim3(3 * Dsz * Dsz / 8 / 256, 2), 256>>>(w_qkv, w_out);

    rmsnorm_kernel<false, true><<<Ntok, 256>>>(x, scale1, nullptr, xnb);
    tc_gemm_bf16<2><<<dim3(24, 16), 256, SMEM_DNB>>>(xnb, wqb, b_qkv, nullptr, qkvb,
                                                     3 * Dsz, Dsz);
    rope_kernel<<<(Ntok * 2 * Hn * 32) / 256, 256>>>(qkvb);
    attn_mma_bf16<<<dim3(Tsz / 128, Hn, Bsz), 256, ATT_SMEM>>>(qkvb, attnb);
    tc_gemm_bf16<1><<<dim3(8, 16), 256, SMEM_DNB>>>(attnb, wob, b_out, x, x1,
                                                    Dsz, Dsz);
    rmsnorm_kernel<true, false><<<Ntok, 256>>>(x1, scale2, xn, nullptr);
    moe_init_kernel<<<1, 32>>>();
    gate_kernel<<<Ntok / 8, 256>>>(xn, w_gate, b_gate);
    moe_offsets_kernel<<<1, 32>>>(out + (out_size - 1));
    moe_scatter_kernel<<<(Ntok + 255) / 256, 256>>>();
    gather_kernel<<<NROWS, 256>>>(xn);

    cudaStreamWaitEvent(0, evB, 0);
    // grid: x = row-block (fastest) so co-resident CTAs share B strips in L2
    moe_up_bf16<<<dim3(32, FFn / 128, En), 256, SMEM_UPB>>>(b1, b2);
    moe_down_bf16<<<dim3(32, Dsz / 128, En), 256, SMEM_DNB>>>(bp);
    combine_kernel<<<(Ntok * Dsz) / 256, 256>>>(x1, out);
}

// round 16
// speedup vs baseline: 1.0396x; 1.0396x over previous
#include <cuda_runtime.h>
#include <cuda_bf16.h>
#include <math.h>
#include <stdint.h>

#define Bsz 2
#define Tsz 1024
#define Dsz 1024
#define Hn  16
#define HDim 64
#define En  8
#define FFn 4096
#define Ntok (Bsz*Tsz)
#define NROWS (Ntok*2)
#define EPSf 1e-5f
#define WELEM (En*Dsz*FFn)

__device__ __align__(1024) float g_xn  [Ntok*Dsz];
__device__ __align__(1024) float g_x1  [Ntok*Dsz];
__device__ __align__(1024) float g_y   [(size_t)NROWS*Dsz];
__device__ __align__(1024) __nv_bfloat16 g_xnb  [Ntok*Dsz];
__device__ __align__(1024) __nv_bfloat16 g_qkvb [Ntok*3*Dsz];
__device__ __align__(1024) __nv_bfloat16 g_attnb[Ntok*Dsz];
__device__ __align__(1024) __nv_bfloat16 g_xgb[(size_t)NROWS*Dsz];
__device__ __align__(1024) __nv_bfloat16 g_hb [(size_t)NROWS*FFn];
__device__ __align__(1024) __nv_bfloat16 g_w1b[(size_t)WELEM];
__device__ __align__(1024) __nv_bfloat16 g_w2b[(size_t)WELEM];
__device__ __align__(1024) __nv_bfloat16 g_wpb[(size_t)WELEM];
__device__ __align__(1024) __nv_bfloat16 g_wqb[Dsz*3*Dsz];
__device__ __align__(1024) __nv_bfloat16 g_wob[Dsz*Dsz];
__device__ int   g_counts[En];
__device__ int   g_offsets[En];
__device__ int   g_cursor[En];
__device__ int   g_rowmap[NROWS];
__device__ int2  g_eidx [Ntok];
__device__ float2 g_gates[Ntok];

// ============ PTX helpers ============
__device__ __forceinline__ uint32_t s2u(const void* p) {
    uint32_t a;
    asm("{ .reg .u64 t; cvta.to.shared.u64 t, %1; cvt.u32.u64 %0, t; }" : "=r"(a) : "l"(p));
    return a;
}
#define CPA16(dst,src) asm volatile("cp.async.cg.shared.global [%0], [%1], 16;" :: "r"((uint32_t)(dst)), "l"(src) : "memory")
#define CPA_COMMIT()   asm volatile("cp.async.commit_group;" ::: "memory")
#define CPA_WAIT3()    asm volatile("cp.async.wait_group 3;" ::: "memory")
#define CPA_WAIT2()    asm volatile("cp.async.wait_group 2;" ::: "memory")
#define CPA_WAIT1()    asm volatile("cp.async.wait_group 1;" ::: "memory")
#define CPA_WAIT0()    asm volatile("cp.async.wait_group 0;" ::: "memory")

__device__ __forceinline__ void mma_bf16(float* c, const uint32_t* a, uint32_t b0, uint32_t b1)
{
    asm volatile("mma.sync.aligned.m16n8k16.row.col.f32.bf16.bf16.f32 "
        "{%0,%1,%2,%3}, {%4,%5,%6,%7}, {%8,%9}, {%0,%1,%2,%3};"
        : "+f"(c[0]), "+f"(c[1]), "+f"(c[2]), "+f"(c[3])
        : "r"(a[0]), "r"(a[1]), "r"(a[2]), "r"(a[3]), "r"(b0), "r"(b1));
}

#define LDM_X4(r, addr) \
    asm volatile("ldmatrix.sync.aligned.m8n8.x4.shared.b16 {%0,%1,%2,%3}, [%4];" \
        : "=r"((r)[0]), "=r"((r)[1]), "=r"((r)[2]), "=r"((r)[3]) : "r"(addr))
#define LDM_X4T(r, addr) \
    asm volatile("ldmatrix.sync.aligned.m8n8.x4.trans.shared.b16 {%0,%1,%2,%3}, [%4];" \
        : "=r"((r)[0]), "=r"((r)[1]), "=r"((r)[2]), "=r"((r)[3]) : "r"(addr))

// ============ bf16 tile geometry ============
// BK=32 (dense attn-side GEMMs)
#define SA 40
#define SB 136
#define A_BYTES (128*SA*2)
#define B_BYTES (32*SB*2)
#define DNSTG (A_BYTES + B_BYTES)
#define SMEM_DNB (4*DNSTG)
// BK=64 (MoE GEMMs)
#define SA2 72
#define A2_BYTES (128*SA2*2)         // 18432
#define B2_BYTES (64*SB*2)           // 17408
#define UPSTG2 (A2_BYTES + 2*B2_BYTES) // 53248
#define DNSTG2 (A2_BYTES + B2_BYTES)   // 35840
#define SMEM_UP2 (3*UPSTG2)            // 159744
#define SMEM_DN2 (3*DNSTG2)            // 107520

// ============ dense bf16 GEMM (BK=32, validated). MODE 1: fp32+resid; MODE 2: bf16 out ============
template<int MODE>
__global__ void __launch_bounds__(256) tc_gemm_bf16(const __nv_bfloat16* __restrict__ A,
                                                    const __nv_bfloat16* __restrict__ B,
                                                    const float* __restrict__ bias,
                                                    const float* __restrict__ resid,
                                                    void* __restrict__ Cout,
                                                    int Nt, int K)
{
    int row0 = blockIdx.y * 128, col0 = blockIdx.x * 128;
    extern __shared__ char smemc[];
    uint32_t smem_u = s2u(smemc);
    int tid = threadIdx.x, lane = tid & 31, wid = tid >> 5;
    int warp_m = wid >> 2, warp_n = wid & 3;
    int lr = lane >> 2, lc = lane & 3;

    float c[4][4][4];
    #pragma unroll
    for (int i = 0; i < 4; i++)
        #pragma unroll
        for (int j = 0; j < 4; j++)
            #pragma unroll
            for (int q = 0; q < 4; q++) c[i][j][q] = 0.f;

    auto load_block = [&](int kb, int s) {
        uint32_t aS = smem_u + s * DNSTG;
        uint32_t bS = aS + A_BYTES;
        #pragma unroll
        for (int i = 0; i < 2; i++) {
            int cc = i * 256 + tid;
            int r = cc >> 2, c8 = cc & 3;
            CPA16(aS + (r * SA + c8 * 8) * 2, A + (size_t)(row0 + r) * K + kb * 32 + c8 * 8);
        }
        #pragma unroll
        for (int i = 0; i < 2; i++) {
            int cc = i * 256 + tid;
            int kr = cc >> 4, n8 = cc & 15;
            CPA16(bS + (kr * SB + n8 * 8) * 2, B + (size_t)(kb * 32 + kr) * Nt + col0 + n8 * 8);
        }
        CPA_COMMIT();
    };

    int NK = K >> 5;
    load_block(0, 0); load_block(1, 1); load_block(2, 2); load_block(3, 3);

    for (int ks = 0; ks < NK; ks++) {
        int s = ks & 3;
        int allow = NK - 1 - ks; if (allow > 3) allow = 3;
        if (allow == 3) CPA_WAIT3(); else if (allow == 2) CPA_WAIT2();
        else if (allow == 1) CPA_WAIT1(); else CPA_WAIT0();
        __syncthreads();
        uint32_t aS = smem_u + s * DNSTG;
        uint32_t bS = aS + A_BYTES;
        #pragma unroll
        for (int k16 = 0; k16 < 2; k16++) {
            uint32_t af[4][4], bf[2][4];
            #pragma unroll
            for (int mt = 0; mt < 4; mt++) {
                uint32_t addr = aS + ((warp_m * 64 + mt * 16 + (lane & 15)) * SA
                                      + k16 * 16 + (lane >> 4) * 8) * 2;
                LDM_X4(af[mt], addr);
            }
            #pragma unroll
            for (int nh = 0; nh < 2; nh++) {
                uint32_t boff = ((k16 * 16 + (lane & 15)) * SB
                                 + warp_n * 32 + nh * 16 + (lane >> 4) * 8) * 2;
                LDM_X4T(bf[nh], bS + boff);
            }
            #pragma unroll
            for (int mt = 0; mt < 4; mt++)
                #pragma unroll
                for (int nt = 0; nt < 4; nt++) {
                    int nh = nt >> 1, p = (nt & 1) * 2;
                    mma_bf16(c[mt][nt], af[mt], bf[nh][p], bf[nh][p + 1]);
                }
        }
        __syncthreads();
        if (ks + 4 < NK) load_block(ks + 4, s);
    }

    #pragma unroll
    for (int mt = 0; mt < 4; mt++) {
        #pragma unroll
        for (int half = 0; half < 2; half++) {
            int orow = row0 + warp_m * 64 + mt * 16 + lr + half * 8;
            #pragma unroll
            for (int nt = 0; nt < 4; nt++) {
                int coll = warp_n * 32 + nt * 8 + lc * 2;
                float v0 = c[mt][nt][half*2]   + bias[col0 + coll];
                float v1 = c[mt][nt][half*2+1] + bias[col0 + coll + 1];
                if (MODE == 1) {
                    const float* Rrow = resid + (size_t)orow * Nt + col0;
                    float2 rv = *(const float2*)(Rrow + coll);
                    v0 += rv.x; v1 += rv.y;
                    *(float2*)((float*)Cout + (size_t)orow * Nt + col0 + coll) = make_float2(v0, v1);
                } else {
                    *(__nv_bfloat162*)((__nv_bfloat16*)Cout + (size_t)orow * Nt + col0 + coll)
                        = __floats2bfloat162_rn(v0, v1);
                }
            }
        }
    }
}

// ============ MoE up: BK=64, 3-stage, dual accumulators ============
__global__ void __launch_bounds__(256) moe_up_bf16(const float* __restrict__ b1,
                                                   const float* __restrict__ b2)
{
    int e = blockIdx.z;
    int cnt = g_counts[e];
    int row0 = blockIdx.y * 128, col0 = blockIdx.x * 128;
    if (row0 >= cnt) return;
    int rowbase = g_offsets[e] + row0;
    b1 += (size_t)e * FFn; b2 += (size_t)e * FFn;
    const __nv_bfloat16* W1 = g_w1b + (size_t)e * Dsz * FFn;
    const __nv_bfloat16* W2 = g_w2b + (size_t)e * Dsz * FFn;

    extern __shared__ char smemc[];
    uint32_t smem_u = s2u(smemc);
    int tid = threadIdx.x, lane = tid & 31, wid = tid >> 5;
    int warp_m = wid >> 2, warp_n = wid & 3;
    int lr = lane >> 2, lc = lane & 3;

    float c1[4][4][4], c2[4][4][4];
    #pragma unroll
    for (int i = 0; i < 4; i++)
        #pragma unroll
        for (int j = 0; j < 4; j++)
            #pragma unroll
            for (int q = 0; q < 4; q++) { c1[i][j][q] = 0.f; c2[i][j][q] = 0.f; }

    auto load_block = [&](int kb, int s) {
        uint32_t aS = smem_u + s * UPSTG2;
        uint32_t b1S = aS + A2_BYTES, b2S = b1S + B2_BYTES;
        #pragma unroll
        for (int i = 0; i < 4; i++) {
            int c = i * 256 + tid;
            int r = c >> 3, c8 = c & 7;
            int gr = rowbase + r; if (gr > NROWS - 1) gr = NROWS - 1;
            CPA16(aS + (r * SA2 + c8 * 8) * 2, g_xgb + (size_t)gr * Dsz + kb * 64 + c8 * 8);
        }
        #pragma unroll
        for (int i = 0; i < 4; i++) {
            int c = i * 256 + tid;
            int kr = c >> 4, n8 = c & 15;
            size_t off = (size_t)(kb * 64 + kr) * FFn + col0 + n8 * 8;
            CPA16(b1S + (kr * SB + n8 * 8) * 2, W1 + off);
            CPA16(b2S + (kr * SB + n8 * 8) * 2, W2 + off);
        }
        CPA_COMMIT();
    };

    const int NK = Dsz >> 6;   // 16
    load_block(0, 0); load_block(1, 1); load_block(2, 2);

    for (int ks = 0; ks < NK; ks++) {
        int s = ks % 3;
        int allow = NK - 1 - ks; if (allow > 2) allow = 2;
        if (allow == 2) CPA_WAIT2(); else if (allow == 1) CPA_WAIT1(); else CPA_WAIT0();
        __syncthreads();
        uint32_t aS = smem_u + s * UPSTG2;
        uint32_t b1S = aS + A2_BYTES, b2S = b1S + B2_BYTES;
        #pragma unroll
        for (int k16 = 0; k16 < 4; k16++) {
            uint32_t af[4][4], bfA[2][4], bfB[2][4];
            #pragma unroll
            for (int mt = 0; mt < 4; mt++) {
                uint32_t addr = aS + ((warp_m * 64 + mt * 16 + (lane & 15)) * SA2
                                      + k16 * 16 + (lane >> 4) * 8) * 2;
                LDM_X4(af[mt], addr);
            }
            #pragma unroll
            for (int nh = 0; nh < 2; nh++) {
                uint32_t boff = ((k16 * 16 + (lane & 15)) * SB
                                 + warp_n * 32 + nh * 16 + (lane >> 4) * 8) * 2;
                LDM_X4T(bfA[nh], b1S + boff);
                LDM_X4T(bfB[nh], b2S + boff);
            }
            #pragma unroll
            for (int mt = 0; mt < 4; mt++)
                #pragma unroll
                for (int nt = 0; nt < 4; nt++) {
                    int nh = nt >> 1, p = (nt & 1) * 2;
                    mma_bf16(c1[mt][nt], af[mt], bfA[nh][p], bfA[nh][p + 1]);
                    mma_bf16(c2[mt][nt], af[mt], bfB[nh][p], bfB[nh][p + 1]);
                }
        }
        __syncthreads();
        if (ks + 3 < NK) load_block(ks + 3, s);
    }

    #pragma unroll
    for (int mt = 0; mt < 4; mt++) {
        #pragma unroll
        for (int half = 0; half < 2; half++) {
            int lrow = warp_m * 64 + mt * 16 + lr + half * 8;
            if ((row0 + lrow) >= cnt) continue;
            __nv_bfloat16* Hrow = g_hb + (size_t)(rowbase + lrow) * FFn + col0;
            #pragma unroll
            for (int nt = 0; nt < 4; nt++) {
                int coll = warp_n * 32 + nt * 8 + lc * 2;
                float u0 = c1[mt][nt][half*2]   + b1[col0 + coll];
                float u1 = c1[mt][nt][half*2+1] + b1[col0 + coll + 1];
                float v0 = c2[mt][nt][half*2]   + b2[col0 + coll];
                float v1 = c2[mt][nt][half*2+1] + b2[col0 + coll + 1];
                float h0 = u0 / (1.f + __expf(-u0)) * v0;
                float h1 = u1 / (1.f + __expf(-u1)) * v1;
                *(__nv_bfloat162*)(Hrow + coll) = __floats2bfloat162_rn(h0, h1);
            }
        }
    }
}

// ============ MoE down: BK=64, 3-stage ============
__global__ void __launch_bounds__(256) moe_down_bf16(const float* __restrict__ bp)
{
    int e = blockIdx.z;
    int cnt = g_counts[e];
    int row0 = blockIdx.y * 128, col0 = blockIdx.x * 128;
    if (row0 >= cnt) return;
    int rowbase = g_offsets[e] + row0;
    bp += (size_t)e * Dsz;
    const __nv_bfloat16* Wp = g_wpb + (size_t)e * FFn * Dsz;

    extern __shared__ char smemc[];
    uint32_t smem_u = s2u(smemc);
    int tid = threadIdx.x, lane = tid & 31, wid = tid >> 5;
    int warp_m = wid >> 2, warp_n = wid & 3;
    int lr = lane >> 2, lc = lane & 3;

    float c[4][4][4];
    #pragma unroll
    for (int i = 0; i < 4; i++)
        #pragma unroll
        for (int j = 0; j < 4; j++)
            #pragma unroll
            for (int q = 0; q < 4; q++) c[i][j][q] = 0.f;

    auto load_block = [&](int kb, int s) {
        uint32_t aS = smem_u + s * DNSTG2;
        uint32_t bS = aS + A2_BYTES;
        #pragma unroll
        for (int i = 0; i < 4; i++) {
            int cc = i * 256 + tid;
            int r = cc >> 3, c8 = cc & 7;
            int gr = rowbase + r; if (gr > NROWS - 1) gr = NROWS - 1;
            CPA16(aS + (r * SA2 + c8 * 8) * 2, g_hb + (size_t)gr * FFn + kb * 64 + c8 * 8);
        }
        #pragma unroll
        for (int i = 0; i < 4; i++) {
            int cc = i * 256 + tid;
            int kr = cc >> 4, n8 = cc & 15;
            CPA16(bS + (kr * SB + n8 * 8) * 2, Wp + (size_t)(kb * 64 + kr) * Dsz + col0 + n8 * 8);
        }
        CPA_COMMIT();
    };

    const int NK = FFn >> 6;   // 64
    load_block(0, 0); load_block(1, 1); load_block(2, 2);

    for (int ks = 0; ks < NK; ks++) {
        int s = ks % 3;
        int allow = NK - 1 - ks; if (allow > 2) allow = 2;
        if (allow == 2) CPA_WAIT2(); else if (allow == 1) CPA_WAIT1(); else CPA_WAIT0();
        __syncthreads();
        uint32_t aS = smem_u + s * DNSTG2;
        uint32_t bS = aS + A2_BYTES;
        #pragma unroll
        for (int k16 = 0; k16 < 4; k16++) {
            uint32_t af[4][4], bf[2][4];
            #pragma unroll
            for (int mt = 0; mt < 4; mt++) {
                uint32_t addr = aS + ((warp_m * 64 + mt * 16 + (lane & 15)) * SA2
                                      + k16 * 16 + (lane >> 4) * 8) * 2;
                LDM_X4(af[mt], addr);
            }
            #pragma unroll
            for (int nh = 0; nh < 2; nh++) {
                uint32_t boff = ((k16 * 16 + (lane & 15)) * SB
                                 + warp_n * 32 + nh * 16 + (lane >> 4) * 8) * 2;
                LDM_X4T(bf[nh], bS + boff);
            }
            #pragma unroll
            for (int mt = 0; mt < 4; mt++)
                #pragma unroll
                for (int nt = 0; nt < 4; nt++) {
                    int nh = nt >> 1, p = (nt & 1) * 2;
                    mma_bf16(c[mt][nt], af[mt], bf[nh][p], bf[nh][p + 1]);
                }
        }
        __syncthreads();
        if (ks + 3 < NK) load_block(ks + 3, s);
    }

    #pragma unroll
    for (int mt = 0; mt < 4; mt++) {
        #pragma unroll
        for (int half = 0; half < 2; half++) {
            int lrow = warp_m * 64 + mt * 16 + lr + half * 8;
            if ((row0 + lrow) >= cnt) continue;
            int packed = g_rowmap[rowbase + lrow];
            float* Yrow = g_y + (size_t)packed * Dsz + col0;
            #pragma unroll
            for (int nt = 0; nt < 4; nt++) {
                int coll = warp_n * 32 + nt * 8 + lc * 2;
                float v0 = c[mt][nt][half*2]   + bp[col0 + coll];
                float v1 = c[mt][nt][half*2+1] + bp[col0 + coll + 1];
                *(float2*)(Yrow + coll) = make_float2(v0, v1);
            }
        }
    }
}

// ============ weight conversions ============
__global__ void __launch_bounds__(256) convert_weights(const float* __restrict__ w1,
                                                       const float* __restrict__ w2,
                                                       const float* __restrict__ wp)
{
    size_t base = ((size_t)blockIdx.x * 256 + threadIdx.x) * 8;
    const float* src = (blockIdx.y == 0) ? w1 : (blockIdx.y == 1) ? w2 : wp;
    __nv_bfloat16* dst = (blockIdx.y == 0) ? g_w1b : (blockIdx.y == 1) ? g_w2b : g_wpb;
    float4 a = *(const float4*)(src + base);
    float4 b = *(const float4*)(src + base + 4);
    __nv_bfloat162 r[4];
    r[0] = __floats2bfloat162_rn(a.x, a.y);
    r[1] = __floats2bfloat162_rn(a.z, a.w);
    r[2] = __floats2bfloat162_rn(b.x, b.y);
    r[3] = __floats2bfloat162_rn(b.z, b.w);
    *(uint4*)(dst + base) = *(uint4*)r;
}

__global__ void __launch_bounds__(256) convert_attn_weights(const float* __restrict__ wq,
                                                            const float* __restrict__ wo)
{
    size_t base = ((size_t)blockIdx.x * 256 + threadIdx.x) * 8;
    const float* src; __nv_bfloat16* dst;
    if (blockIdx.y == 0) { src = wq; dst = g_wqb; }
    else { if (base >= (size_t)Dsz * Dsz) return; src = wo; dst = g_wob; }
    float4 a = *(const float4*)(src + base);
    float4 b = *(const float4*)(src + base + 4);
    __nv_bfloat162 r[4];
    r[0] = __floats2bfloat162_rn(a.x, a.y);
    r[1] = __floats2bfloat162_rn(a.z, a.w);
    r[2] = __floats2bfloat162_rn(b.x, b.y);
    r[3] = __floats2bfloat162_rn(b.z, b.w);
    *(uint4*)(dst + base) = *(uint4*)r;
}

// ============ bf16 tensor-core flash attention (validated R13) ============
#define SK 72
#define ATT_SMEM ((128*SK + 4*64*SK + 128*SK)*2)

__global__ void __launch_bounds__(256) attn_mma_bf16(const __nv_bfloat16* __restrict__ qkv,
                                                     __nv_bfloat16* __restrict__ O)
{
    extern __shared__ __nv_bfloat16 smh[];
    __nv_bfloat16* Qs = smh;
    __nv_bfloat16* Kb = Qs + 128 * SK;
    __nv_bfloat16* Vb = Kb + 2 * 64 * SK;
    __nv_bfloat16* Ps = Vb + 2 * 64 * SK;
    const int qt = gridDim.x - 1 - blockIdx.x;
    const int h = blockIdx.y, b = blockIdx.z;
    const int q0 = qt * 128;
    int tid = threadIdx.x, lane = tid & 31, wid = tid >> 5;
    int lr = lane >> 2, lc = lane & 3;
    int wm = wid * 16;

    uint32_t qsU = s2u(Qs), kbU = s2u(Kb), vbU = s2u(Vb), psU = s2u(Ps);

    #pragma unroll
    for (int i = 0; i < 4; i++) {
        int idx = i * 256 + tid;
        int r = idx >> 3, c8 = idx & 7;
        CPA16(qsU + (r * SK + c8 * 8) * 2,
              qkv + (size_t)(b * Tsz + q0 + r) * (3 * Dsz) + h * HDim + c8 * 8);
    }
    CPA_COMMIT();

    auto loadKV = [&](int kt) {
        int s = kt & 1;
        uint32_t kU = kbU + s * 64 * SK * 2;
        uint32_t vU = vbU + s * 64 * SK * 2;
        int k0g = kt * 64;
        #pragma unroll
        for (int i = 0; i < 2; i++) {
            int idx = i * 256 + tid;
            int r = idx >> 3, c8 = idx & 7;
            const __nv_bfloat16* src = qkv + (size_t)(b * Tsz + k0g + r) * (3 * Dsz)
                                       + Dsz + h * HDim + c8 * 8;
            CPA16(kU + (r * SK + c8 * 8) * 2, src);
            CPA16(vU + (r * SK + c8 * 8) * 2, src + Dsz);
        }
        CPA_COMMIT();
    };

    float accO[8][4];
    #pragma unroll
    for (int nt = 0; nt < 8; nt++)
        #pragma unroll
        for (int q = 0; q < 4; q++) accO[nt][q] = 0.f;
    float m0 = -1e30f, m1 = -1e30f, l0 = 0.f, l1 = 0.f;

    int row0g = q0 + wm + lr, row1g = row0g + 8;
    int ktmax = qt * 2 + 2;

    int kn_row = (lane & 7) + ((lane >> 4) << 3);
    int kn_koff = ((lane >> 3) & 1) * 8;

    loadKV(0);
    for (int kt = 0; kt < ktmax; kt++) {
        int k0g = kt * 64;
        if (kt + 1 < ktmax) { loadKV(kt + 1); CPA_WAIT1(); }
        else CPA_WAIT0();
        __syncthreads();
        uint32_t ksU2 = kbU + (kt & 1) * 64 * SK * 2;
        uint32_t vsU2 = vbU + (kt & 1) * 64 * SK * 2;

        float cS[8][4];
        #pragma unroll
        for (int nt = 0; nt < 8; nt++)
            #pragma unroll
            for (int q = 0; q < 4; q++) cS[nt][q] = 0.f;
        #pragma unroll
        for (int k16 = 0; k16 < 4; k16++) {
            uint32_t aq[4];
            LDM_X4(aq, qsU + ((wm + (lane & 15)) * SK + k16 * 16 + (lane >> 4) * 8) * 2);
            #pragma unroll
            for (int nt2 = 0; nt2 < 4; nt2++) {
                uint32_t bk[4];
                LDM_X4(bk, ksU2 + ((nt2 * 16 + kn_row) * SK + k16 * 16 + kn_koff) * 2);
                mma_bf16(cS[nt2 * 2],     aq, bk[0], bk[1]);
                mma_bf16(cS[nt2 * 2 + 1], aq, bk[2], bk[3]);
            }
        }

        float mx0 = -1e30f, mx1 = -1e30f;
        #pragma unroll
        for (int nt = 0; nt < 8; nt++) {
            int colb = k0g + nt * 8 + 2 * lc;
            float s00 = cS[nt][0] * 0.125f; if (colb     > row0g) s00 = -1e30f;
            float s01 = cS[nt][1] * 0.125f; if (colb + 1 > row0g) s01 = -1e30f;
            float s10 = cS[nt][2] * 0.125f; if (colb     > row1g) s10 = -1e30f;
            float s11 = cS[nt][3] * 0.125f; if (colb + 1 > row1g) s11 = -1e30f;
            cS[nt][0] = s00; cS[nt][1] = s01; cS[nt][2] = s10; cS[nt][3] = s11;
            mx0 = fmaxf(mx0, fmaxf(s00, s01));
            mx1 = fmaxf(mx1, fmaxf(s10, s11));
        }
        mx0 = fmaxf(mx0, __shfl_xor_sync(0xffffffffu, mx0, 1));
        mx0 = fmaxf(mx0, __shfl_xor_sync(0xffffffffu, mx0, 2));
        mx1 = fmaxf(mx1, __shfl_xor_sync(0xffffffffu, mx1, 1));
        mx1 = fmaxf(mx1, __shfl_xor_sync(0xffffffffu, mx1, 2));
        float mn0 = fmaxf(m0, mx0), mn1 = fmaxf(m1, mx1);
        float ls0 = 0.f, ls1 = 0.f;
        __nv_bfloat16* pr0 = Ps + (wm + lr) * SK;
        __nv_bfloat16* pr1 = Ps + (wm + lr + 8) * SK;
        #pragma unroll
        for (int nt = 0; nt < 8; nt++) {
            float p00 = __expf(cS[nt][0] - mn0);
            float p01 = __expf(cS[nt][1] - mn0);
            float p10 = __expf(cS[nt][2] - mn1);
            float p11 = __expf(cS[nt][3] - mn1);
            ls0 += p00 + p01; ls1 += p10 + p11;
            int cb = nt * 8 + 2 * lc;
            *(__nv_bfloat162*)(pr0 + cb) = __floats2bfloat162_rn(p00, p01);
            *(__nv_bfloat162*)(pr1 + cb) = __floats2bfloat162_rn(p10, p11);
        }
        ls0 += __shfl_xor_sync(0xffffffffu, ls0, 1);
        ls0 += __shfl_xor_sync(0xffffffffu, ls0, 2);
        ls1 += __shfl_xor_sync(0xffffffffu, ls1, 1);
        ls1 += __shfl_xor_sync(0xffffffffu, ls1, 2);
        float alpha0 = __expf(m0 - mn0), alpha1 = __expf(m1 - mn1);
        m0 = mn0; m1 = mn1;
        l0 = l0 * alpha0 + ls0;
        l1 = l1 * alpha1 + ls1;
        #pragma unroll
        for (int nt = 0; nt < 8; nt++) {
            accO[nt][0] *= alpha0; accO[nt][1] *= alpha0;
            accO[nt][2] *= alpha1; accO[nt][3] *= alpha1;
        }
        __syncwarp();

        #pragma unroll
        for (int k16 = 0; k16 < 4; k16++) {
            uint32_t ap[4];
            LDM_X4(ap, psU + ((wm + (lane & 15)) * SK + k16 * 16 + (lane >> 4) * 8) * 2);
            #pragma unroll
            for (int nh = 0; nh < 4; nh++) {
                uint32_t bv[4];
                LDM_X4T(bv, vsU2 + ((k16 * 16 + (lane & 15)) * SK + nh * 16 + (lane >> 4) * 8) * 2);
                mma_bf16(accO[nh * 2],     ap, bv[0], bv[1]);
                mma_bf16(accO[nh * 2 + 1], ap, bv[2], bv[3]);
            }
        }
        __syncthreads();
    }

    float inv0 = 1.0f / l0, inv1 = 1.0f / l1;
    __nv_bfloat16* o0 = O + (size_t)(b * Tsz + row0g) * Dsz + h * HDim;
    __nv_bfloat16* o1 = O + (size_t)(b * Tsz + row1g) * Dsz + h * HDim;
    #pragma unroll
    for (int nt = 0; nt < 8; nt++) {
        int cb = nt * 8 + 2 * lc;
        *(__nv_bfloat162*)(o0 + cb) = __floats2bfloat162_rn(accO[nt][0] * inv0, accO[nt][1] * inv0);
        *(__nv_bfloat162*)(o1 + cb) = __floats2bfloat162_rn(accO[nt][2] * inv1, accO[nt][3] * inv1);
    }
}

// ============ elementwise / routing ============
template<bool WF32, bool WB16>
__global__ void __launch_bounds__(256) rmsnorm_kernel(const float* __restrict__ x,
                                                      const float* __restrict__ scale,
                                                      float* __restrict__ out,
                                                      __nv_bfloat16* __restrict__ outb)
{
    int n = blockIdx.x;
    const float* xr = x + (size_t)n * Dsz;
    float s = 0.f;
    for (int d = threadIdx.x; d < Dsz; d += 256) { float v = xr[d]; s += v * v; }
    __shared__ float red[8];
    for (int o = 16; o; o >>= 1) s += __shfl_xor_sync(0xffffffffu, s, o);
    if ((threadIdx.x & 31) == 0) red[threadIdx.x >> 5] = s;
    __syncthreads();
    if (threadIdx.x < 32) {
        float v = (threadIdx.x < 8) ? red[threadIdx.x] : 0.f;
        for (int o = 4; o; o >>= 1) v += __shfl_xor_sync(0xffffffffu, v, o);
        if (threadIdx.x == 0) red[0] = v;
    }
    __syncthreads();
    float inv = 1.0f / (sqrtf(red[0] / (float)Dsz) + EPSf);
    for (int d = threadIdx.x * 2; d < Dsz; d += 512) {
        float v0 = xr[d] * inv * scale[d];
        float v1 = xr[d + 1] * inv * scale[d + 1];
        if (WF32) *(float2*)(out + (size_t)n * Dsz + d) = make_float2(v0, v1);
        if (WB16) *(__nv_bfloat162*)(outb + (size_t)n * Dsz + d) = __floats2bfloat162_rn(v0, v1);
    }
}

__global__ void __launch_bounds__(256) rope_kernel(__nv_bfloat16* __restrict__ qkv)
{
    int i = blockIdx.x * 256 + threadIdx.x;
    int j = i & 31, h = (i >> 5) & 15, which = (i >> 9) & 1, n = i >> 10;
    int t = n & (Tsz - 1);
    float theta = powf(10000.0f, -(2.0f * (float)j) / (float)HDim);
    float s, c; sincosf((float)t * theta, &s, &c);
    __nv_bfloat16* base = qkv + (size_t)n * (3 * Dsz) + which * Dsz + h * HDim;
    float x1 = __bfloat162float(base[j]);
    float x2 = __bfloat162float(base[j + 32]);
    base[j]      = __float2bfloat16(x1 * c - x2 * s);
    base[j + 32] = __float2bfloat16(x1 * s + x2 * c);
}

__global__ void moe_init_kernel() {
    int i = threadIdx.x;
    if (i < En) { g_counts[i] = 0; g_cursor[i] = 0; }
}

__global__ void __launch_bounds__(256) gate_kernel(const float* __restrict__ xn,
                                                   const float* __restrict__ w_gate,
                                                   const float* __restrict__ b_gate)
{
    int n = blockIdx.x * 8 + (threadIdx.x >> 5);
    int lane = threadIdx.x & 31;
    float acc[En];
    #pragma unroll
    for (int e = 0; e < En; e++) acc[e] = 0.f;
    const float* xr = xn + (size_t)n * Dsz;
    for (int d = lane; d < Dsz; d += 32) {
        float xv = xr[d];
        const float* wr = w_gate + (size_t)d * En;
        #pragma unroll
        for (int e = 0; e < En; e++) acc[e] += xv * wr[e];
    }
    #pragma unroll
    for (int e = 0; e < En; e++)
        #pragma unroll
        for (int o = 16; o; o >>= 1) acc[e] += __shfl_xor_sync(0xffffffffu, acc[e], o);
    if (lane == 0) {
        #pragma unroll
        for (int e = 0; e < En; e++) acc[e] += b_gate[e];
        int e0 = 0; float v0 = acc[0];
        #pragma unroll
        for (int e = 1; e < En; e++) if (acc[e] > v0) { v0 = acc[e]; e0 = e; }
        int e1 = -1; float v1 = -1e30f;
        #pragma unroll
        for (int e = 0; e < En; e++) if (e != e0 && acc[e] > v1) { v1 = acc[e]; e1 = e; }
        float g0 = 1.0f / (1.0f + __expf(v1 - v0));
        atomicAdd(&g_counts[e0], 1);
        atomicAdd(&g_counts[e1], 1);
        g_eidx[n] = make_int2(e0, e1);
        g_gates[n] = make_float2(g0, 1.0f - g0);
    }
}

__global__ void moe_offsets_kernel(float* __restrict__ aux_out)
{
    if (threadIdx.x == 0) {
        int off = 0; float aux = 0.f;
        #pragma unroll
        for (int e = 0; e < En; e++) { g_offsets[e] = off; off += g_counts[e]; }
        #pragma unroll
        for (int e = 0; e < En; e++) {
            float f = (float)g_counts[e] / (float)NROWS - 1.0f / (float)En;
            aux += f * f;
        }
        *aux_out = aux;
    }
}

__global__ void __launch_bounds__(256) moe_scatter_kernel()
{
    int n = blockIdx.x * 256 + threadIdx.x;
    if (n >= Ntok) return;
    int2 e = g_eidx[n];
    int p0 = atomicAdd(&g_cursor[e.x], 1);
    g_rowmap[g_offsets[e.x] + p0] = n * 2;
    int p1 = atomicAdd(&g_cursor[e.y], 1);
    g_rowmap[g_offsets[e.y] + p1] = n * 2 + 1;
}

__global__ void __launch_bounds__(256) gather_kernel(const float* __restrict__ xn)
{
    int r = blockIdx.x;
    int tok = g_rowmap[r] >> 1;
    float4 v = *(const float4*)(xn + (size_t)tok * Dsz + threadIdx.x * 4);
    __nv_bfloat162 p0 = __floats2bfloat162_rn(v.x, v.y);
    __nv_bfloat162 p1 = __floats2bfloat162_rn(v.z, v.w);
    __nv_bfloat162 pr[2] = {p0, p1};
    *(uint2*)(g_xgb + (size_t)r * Dsz + threadIdx.x * 4) = *(uint2*)pr;
}

__global__ void __launch_bounds__(256) combine_kernel(const float* __restrict__ x1,
                                                      float* __restrict__ out)
{
    int i = blockIdx.x * 256 + threadIdx.x;
    int n = i >> 10, d = i & 1023;
    float2 g = g_gates[n];
    float y0 = g_y[(size_t)(n * 2) * Dsz + d];
    float y1 = g_y[(size_t)(n * 2 + 1) * Dsz + d];
    out[i] = x1[i] + g.x * y0 + g.y * y1;
}

// ============ launch ============
extern "C" void kernel_launch(void* const* d_in, const int* in_sizes, int n_in,
                              void* d_out, int out_size)
{
    const float* x      = (const float*)d_in[0];
    const float* w_qkv  = (const float*)d_in[1];
    const float* b_qkv  = (const float*)d_in[2];
    const float* w_out  = (const float*)d_in[3];
    const float* b_out  = (const float*)d_in[4];
    const float* scale1 = (const float*)d_in[5];
    const float* scale2 = (const float*)d_in[6];
    const float* w_gate = (const float*)d_in[7];
    const float* b_gate = (const float*)d_in[8];
    const float* w1     = (const float*)d_in[9];
    const float* b1     = (const float*)d_in[10];
    const float* w2     = (const float*)d_in[11];
    const float* b2     = (const float*)d_in[12];
    const float* wp     = (const float*)d_in[13];
    const float* bp     = (const float*)d_in[14];
    float* out = (float*)d_out;

    float* xn   = nullptr; cudaGetSymbolAddress((void**)&xn,   g_xn);
    float* x1   = nullptr; cudaGetSymbolAddress((void**)&x1,   g_x1);
    __nv_bfloat16* xnb   = nullptr; cudaGetSymbolAddress((void**)&xnb,   g_xnb);
    __nv_bfloat16* qkvb  = nullptr; cudaGetSymbolAddress((void**)&qkvb,  g_qkvb);
    __nv_bfloat16* attnb = nullptr; cudaGetSymbolAddress((void**)&attnb, g_attnb);
    __nv_bfloat16* wqb   = nullptr; cudaGetSymbolAddress((void**)&wqb,   g_wqb);
    __nv_bfloat16* wob   = nullptr; cudaGetSymbolAddress((void**)&wob,   g_wob);

    static cudaStream_t s2;
    static cudaEvent_t evA, evB;
    static bool init_done = false;
    if (!init_done) {
        cudaStreamCreateWithFlags(&s2, cudaStreamNonBlocking);
        cudaEventCreateWithFlags(&evA, cudaEventDisableTiming);
        cudaEventCreateWithFlags(&evB, cudaEventDisableTiming);
        cudaFuncSetAttribute(tc_gemm_bf16<1>, cudaFuncAttributeMaxDynamicSharedMemorySize, SMEM_DNB);
        cudaFuncSetAttribute(tc_gemm_bf16<2>, cudaFuncAttributeMaxDynamicSharedMemorySize, SMEM_DNB);
        cudaFuncSetAttribute(moe_up_bf16,     cudaFuncAttributeMaxDynamicSharedMemorySize, SMEM_UP2);
        cudaFuncSetAttribute(moe_down_bf16,   cudaFuncAttributeMaxDynamicSharedMemorySize, SMEM_DN2);
        cudaFuncSetAttribute(attn_mma_bf16,   cudaFuncAttributeMaxDynamicSharedMemorySize, ATT_SMEM);
        init_done = true;
    }

    cudaEventRecord(evA, 0);
    cudaStreamWaitEvent(s2, evA, 0);
    convert_weights<<<dim3(WELEM / 8 / 256, 3), 256, 0, s2>>>(w1, w2, wp);
    cudaEventRecord(evB, s2);

    convert_attn_weights<<<dim3(3 * Dsz * Dsz / 8 / 256, 2), 256>>>(w_qkv, w_out);

    rmsnorm_kernel<false, true><<<Ntok, 256>>>(x, scale1, nullptr, xnb);
    tc_gemm_bf16<2><<<dim3(24, 16), 256, SMEM_DNB>>>(xnb, wqb, b_qkv, nullptr, qkvb,
                                                     3 * Dsz, Dsz);
    rope_kernel<<<(Ntok * 2 * Hn * 32) / 256, 256>>>(qkvb);
    attn_mma_bf16<<<dim3(Tsz / 128, Hn, Bsz), 256, ATT_SMEM>>>(qkvb, attnb);
    tc_gemm_bf16<1><<<dim3(8, 16), 256, SMEM_DNB>>>(attnb, wob, b_out, x, x1,
                                                    Dsz, Dsz);
    rmsnorm_kernel<true, false><<<Ntok, 256>>>(x1, scale2, xn, nullptr);
    moe_init_kernel<<<1, 32>>>();
    gate_kernel<<<Ntok / 8, 256>>>(xn, w_gate, b_gate);
    moe_offsets_kernel<<<1, 32>>>(out + (out_size - 1));
    moe_scatter_kernel<<<(Ntok + 255) / 256, 256>>>();
    gather_kernel<<<NROWS, 256>>>(xn);

    cudaStreamWaitEvent(0, evB, 0);
    moe_up_bf16<<<dim3(FFn / 128, 32, En), 256, SMEM_UP2>>>(b1, b2);
    moe_down_bf16<<<dim3(Dsz / 128, 32, En), 256, SMEM_DN2>>>(bp);
    combine_kernel<<<(Ntok * Dsz) / 256, 256>>>(x1, out);
}